// round 3
// baseline (speedup 1.0000x reference)
#include <cuda_runtime.h>

// Problem constants
#define SQ    1024      // sequence length
#define BATCH 2048
#define H     128
#define KD    2         // input dim
#define JP    64        // H/2 (f32x2 pairs)
#define NCTA  128
#define MB    16        // batch per CTA
#define TPB   256       // threads per CTA: 128 row-groups x 2 batch-groups

typedef unsigned long long ull;

__device__ __forceinline__ ull pack2(float lo, float hi) {
    ull r; asm("mov.b64 %0, {%1,%2};" : "=l"(r) : "f"(lo), "f"(hi)); return r;
}
__device__ __forceinline__ void unpack2(ull v, float& lo, float& hi) {
    asm("mov.b64 {%0,%1}, %2;" : "=f"(lo), "=f"(hi) : "l"(v));
}
__device__ __forceinline__ void fma2(ull& acc, ull a, ull b) {
    asm("fma.rn.f32x2 %0, %1, %2, %0;" : "+l"(acc) : "l"(a), "l"(b));
}

// ~1-ulp expf, immune to fast-math (explicit fmaf + bit tricks only).
// Cephes-style: n = rint(x*log2e), r = x - n*ln2 (2-part), poly on r, scale 2^n.
__device__ __forceinline__ float exp_acc(float x) {
    x = fminf(fmaxf(x, -87.0f), 88.0f);
    const float LOG2E  = 1.4426950408889634f;
    const float LN2_HI = 0.6931471824645996f;
    const float LN2_LO = -1.9046542743e-09f;
    float n = rintf(x * LOG2E);
    float r = fmaf(-n, LN2_HI, x);
    r = fmaf(-n, LN2_LO, r);
    float p = 1.9875691500e-4f;
    p = fmaf(p, r, 1.3981999507e-3f);
    p = fmaf(p, r, 8.3334519073e-3f);
    p = fmaf(p, r, 4.1665795894e-2f);
    p = fmaf(p, r, 1.6666665459e-1f);
    p = fmaf(p, r, 5.0000001201e-1f);
    float e = fmaf(p * r, r, r) + 1.0f;      // exp(r) = 1 + r + r^2*P(r)
    int ni = (int)n;
    float sc = __int_as_float((ni + 127) << 23);
    return e * sc;
}
__device__ __forceinline__ float sigmoid_acc(float v) {
    return 1.0f / (1.0f + exp_acc(-v));
}

// ---- device scratch: weights pre-packed as f32x2, layout [jp][h] ----
__device__ ull g_w1spk[JP * H];   // W1x[:, 2+2jp], W1x[:, 3+2jp]
__device__ ull g_wmd[JP * H];     // WtauM dense-part cols [0,128)
__device__ ull g_wmm[JP * H];     // WtauM mem-part   cols [128,256)
__device__ ull g_wad[JP * H];     // WtauAdp dense-part
__device__ ull g_wab[JP * H];     // WtauAdp bb-part
__device__ float g_partial[NCTA];

__global__ void pack_kernel(const float* __restrict__ W1x,
                            const float* __restrict__ WtauM,
                            const float* __restrict__ WtauAdp) {
    int i = blockIdx.x * blockDim.x + threadIdx.x;
    if (i >= JP * H) return;
    int jp = i / H, h = i % H;
    g_w1spk[i] = pack2(W1x[h * 130 + 2 + 2 * jp], W1x[h * 130 + 3 + 2 * jp]);
    g_wmd[i]   = pack2(WtauM[h * 256 + 2 * jp],       WtauM[h * 256 + 2 * jp + 1]);
    g_wmm[i]   = pack2(WtauM[h * 256 + 128 + 2 * jp], WtauM[h * 256 + 129 + 2 * jp]);
    g_wad[i]   = pack2(WtauAdp[h * 256 + 2 * jp],       WtauAdp[h * 256 + 2 * jp + 1]);
    g_wab[i]   = pack2(WtauAdp[h * 256 + 128 + 2 * jp], WtauAdp[h * 256 + 129 + 2 * jp]);
}

// MAC loop over one K=128 block: acc[i] (f32x2, even/odd j lanes) for 8 batch, 1 row h.
// Weights from SMEM.
__device__ __forceinline__ void mac8_s(const ull* __restrict__ w,
                                       const float* __restrict__ a,
                                       ull acc[8], int h, int m0) {
#pragma unroll 4
    for (int jp = 0; jp < JP; jp += 2) {
        ull w0 = w[jp * H + h];
        ull w1 = w[(jp + 1) * H + h];
#pragma unroll
        for (int i = 0; i < 8; i++) {
            ulonglong2 av = *(const ulonglong2*)&a[(m0 + i) * H + 2 * jp];
            fma2(acc[i], w0, av.x);
            fma2(acc[i], w1, av.y);
        }
    }
}

// Same but weights streamed from global (L2): deeper unroll for MLP.
__device__ __forceinline__ void mac8_g(const ull* __restrict__ w,
                                       const float* __restrict__ a,
                                       ull acc[8], int h, int m0) {
#pragma unroll 8
    for (int jp = 0; jp < JP; jp += 2) {
        ull w0 = __ldg(&w[jp * H + h]);
        ull w1 = __ldg(&w[(jp + 1) * H + h]);
#pragma unroll
        for (int i = 0; i < 8; i++) {
            ulonglong2 av = *(const ulonglong2*)&a[(m0 + i) * H + 2 * jp];
            fma2(acc[i], w0, av.x);
            fma2(acc[i], w1, av.y);
        }
    }
}

__global__ void __launch_bounds__(TPB, 1)
rnn_kernel(const float* __restrict__ x,   const float* __restrict__ y,
           const float* __restrict__ h0m, const float* __restrict__ h0s,
           const float* __restrict__ h0b,
           const float* __restrict__ W1x, const float* __restrict__ b1x,
           const float* __restrict__ btauM, const float* __restrict__ btauAdp,
           const float* __restrict__ Wlin,  const float* __restrict__ blin) {
    extern __shared__ ull sh[];
    ull* sw1  = sh;                 // 64KB
    ull* swmd = sh + JP * H;        // 64KB
    ull* swad = sh + 2 * JP * H;    // 64KB
    float* aspk = (float*)(sh + 3 * JP * H);   // [MB][H]
    float* amem = aspk + MB * H;
    float* abb  = amem + MB * H;
    float* aden = abb + MB * H;

    const int tid = threadIdx.x;
    const int h   = tid & 127;          // row owned by this thread
    const int bg  = tid >> 7;           // 0..1
    const int m0  = bg * 8;             // first of 8 batch elems
    const int gmb = blockIdx.x * MB;    // global batch base

    // stage smem weights (coalesced from pre-packed scratch)
    for (int i = tid; i < JP * H; i += TPB) {
        sw1[i]  = g_w1spk[i];
        swmd[i] = g_wmd[i];
        swad[i] = g_wad[i];
    }
    // init states
    for (int i = tid; i < MB * H; i += TPB) {
        int m = i >> 7, hh = i & 127;
        aspk[i] = h0s[(gmb + m) * H + hh];
        amem[i] = h0m[(gmb + m) * H + hh];
        abb[i]  = h0b[(gmb + m) * H + hh];
    }
    // per-row constants
    const float xw0 = W1x[h * 130 + 0];
    const float xw1 = W1x[h * 130 + 1];
    const float b1  = b1x[h];
    const float bm  = btauM[h];
    const float ba  = btauAdp[h];
    __syncthreads();

    for (int t = 0; t < SQ; t++) {
        // x_t for my 8 batch elems
        float2 xv[8];
#pragma unroll
        for (int i = 0; i < 8; i++)
            xv[i] = *(const float2*)&x[((long)t * BATCH + gmb + m0 + i) * KD];

        // ---- phase A: dense = W1x_spk @ spk (+ x part + bias) ----
        ull acc[8];
#pragma unroll
        for (int i = 0; i < 8; i++) acc[i] = 0ull;
        mac8_s(sw1, aspk, acc, h, m0);
#pragma unroll
        for (int i = 0; i < 8; i++) {
            float lo, hi; unpack2(acc[i], lo, hi);
            aden[(m0 + i) * H + h] = lo + hi + b1 + xw0 * xv[i].x + xw1 * xv[i].y;
        }
        __syncthreads();   // dense visible

        // ---- phase B: tauM pre-activation ----
#pragma unroll
        for (int i = 0; i < 8; i++) acc[i] = 0ull;
        mac8_s(swmd, aden, acc, h, m0);
        mac8_g(g_wmm, amem, acc, h, m0);
        float tm[8];
#pragma unroll
        for (int i = 0; i < 8; i++) {
            float lo, hi; unpack2(acc[i], lo, hi);
            tm[i] = sigmoid_acc(lo + hi + bm);
        }
        // ---- tauA pre-activation ----
#pragma unroll
        for (int i = 0; i < 8; i++) acc[i] = 0ull;
        mac8_s(swad, aden, acc, h, m0);
        mac8_g(g_wab, abb, acc, h, m0);
        float ta[8];
#pragma unroll
        for (int i = 0; i < 8; i++) {
            float lo, hi; unpack2(acc[i], lo, hi);
            ta[i] = sigmoid_acc(lo + hi + ba);
        }
        __syncthreads();   // all reads of mem/bb/dense/spk done

        // ---- phase C: elementwise state update (own cells only) ----
#pragma unroll
        for (int i = 0; i < 8; i++) {
            int idx = (m0 + i) * H + h;
            float sp = aspk[idx];
            float me = amem[idx];
            float bo = abb[idx];
            float de = aden[idx];
            float bbn = ta[i] * bo + (1.0f - ta[i]) * sp;
            float Bth = 0.01f + 1.8f * bbn;
            float mn  = me * tm[i] + (1.0f - tm[i]) * de - Bth * sp;
            float sn  = (mn - Bth) > 0.0f ? 1.0f : 0.0f;
            amem[idx] = mn;
            aspk[idx] = sn;
            abb[idx]  = bbn;
        }
        __syncthreads();   // states visible for next step
    }

    // ---- readout: out[m] = mem[m] . Wlin + blin ; partial sum of (out-y)^2 ----
    if (tid < MB) {
        float o = blin[0];
        for (int hh = 0; hh < H; hh++) o += amem[tid * H + hh] * Wlin[hh];
        float d = o - y[gmb + tid];
        aden[tid] = d * d;   // reuse buffer
    }
    __syncthreads();
    if (tid == 0) {
        float s = 0.0f;
        for (int i = 0; i < MB; i++) s += aden[i];
        g_partial[blockIdx.x] = s;
    }
}

__global__ void reduce_kernel(float* out) {
    __shared__ float sb[NCTA];
    sb[threadIdx.x] = g_partial[threadIdx.x];
    __syncthreads();
    if (threadIdx.x == 0) {
        float s = 0.0f;
        for (int i = 0; i < NCTA; i++) s += sb[i];
        out[0] = s / (float)BATCH;
    }
}

extern "C" void kernel_launch(void* const* d_in, const int* in_sizes, int n_in,
                              void* d_out, int out_size) {
    const float* x       = (const float*)d_in[0];
    const float* y       = (const float*)d_in[1];
    const float* h0_mem  = (const float*)d_in[2];
    const float* h0_spk  = (const float*)d_in[3];
    const float* h0_b    = (const float*)d_in[4];
    const float* W1x     = (const float*)d_in[5];
    const float* b1x     = (const float*)d_in[6];
    const float* WtauM   = (const float*)d_in[7];
    const float* btauM   = (const float*)d_in[8];
    const float* WtauAdp = (const float*)d_in[9];
    const float* btauAdp = (const float*)d_in[10];
    const float* Wlin    = (const float*)d_in[11];
    const float* blin    = (const float*)d_in[12];

    const int smem_bytes = 3 * JP * H * (int)sizeof(ull) + 4 * MB * H * (int)sizeof(float);
    static int attr_set = 0;
    if (!attr_set) {
        cudaFuncSetAttribute(rnn_kernel, cudaFuncAttributeMaxDynamicSharedMemorySize, smem_bytes);
        attr_set = 1;
    }

    pack_kernel<<<(JP * H + 255) / 256, 256>>>(W1x, WtauM, WtauAdp);
    rnn_kernel<<<NCTA, TPB, smem_bytes>>>(x, y, h0_mem, h0_spk, h0_b,
                                          W1x, b1x, btauM, btauAdp, Wlin, blin);
    reduce_kernel<<<1, NCTA>>>((float*)d_out);
}

// round 4
// speedup vs baseline: 1.0118x; 1.0118x over previous
#include <cuda_runtime.h>

// Problem constants
#define SQ    1024      // sequence length
#define BATCH 2048
#define H     128
#define KD    2         // input dim
#define JP    64        // H/2 (f32x2 pairs)
#define NCTA  128
#define MB    16        // batch per CTA
#define TPB   512       // 128 rows x 4 batch-groups
#define MT    4         // batch elems per thread

typedef unsigned long long ull;

__device__ __forceinline__ ull pack2(float lo, float hi) {
    ull r; asm("mov.b64 %0, {%1,%2};" : "=l"(r) : "f"(lo), "f"(hi)); return r;
}
__device__ __forceinline__ void unpack2(ull v, float& lo, float& hi) {
    asm("mov.b64 {%0,%1}, %2;" : "=f"(lo), "=f"(hi) : "l"(v));
}
__device__ __forceinline__ void fma2(ull& acc, ull a, ull b) {
    asm("fma.rn.f32x2 %0, %1, %2, %0;" : "+l"(acc) : "l"(a), "l"(b));
}

// ~1-ulp expf, immune to fast-math (explicit fmaf + bit tricks only).
__device__ __forceinline__ float exp_acc(float x) {
    x = fminf(fmaxf(x, -87.0f), 88.0f);
    const float LOG2E  = 1.4426950408889634f;
    const float LN2_HI = 0.6931471824645996f;
    const float LN2_LO = -1.9046542743e-09f;
    float n = rintf(x * LOG2E);
    float r = fmaf(-n, LN2_HI, x);
    r = fmaf(-n, LN2_LO, r);
    float p = 1.9875691500e-4f;
    p = fmaf(p, r, 1.3981999507e-3f);
    p = fmaf(p, r, 8.3334519073e-3f);
    p = fmaf(p, r, 4.1665795894e-2f);
    p = fmaf(p, r, 1.6666665459e-1f);
    p = fmaf(p, r, 5.0000001201e-1f);
    float e = fmaf(p * r, r, r) + 1.0f;
    int ni = (int)n;
    float sc = __int_as_float((ni + 127) << 23);
    return e * sc;
}
__device__ __forceinline__ float sigmoid_acc(float v) {
    return 1.0f / (1.0f + exp_acc(-v));
}

// ---- device scratch: weights pre-packed as f32x2, layout [jp][h] ----
__device__ ull g_w1spk[JP * H];
__device__ ull g_wmd[JP * H];
__device__ ull g_wmm[JP * H];
__device__ ull g_wad[JP * H];
__device__ ull g_wab[JP * H];
__device__ float g_partial[NCTA];

__global__ void pack_kernel(const float* __restrict__ W1x,
                            const float* __restrict__ WtauM,
                            const float* __restrict__ WtauAdp) {
    int i = blockIdx.x * blockDim.x + threadIdx.x;
    if (i >= JP * H) return;
    int jp = i / H, h = i % H;
    g_w1spk[i] = pack2(W1x[h * 130 + 2 + 2 * jp], W1x[h * 130 + 3 + 2 * jp]);
    g_wmd[i]   = pack2(WtauM[h * 256 + 2 * jp],       WtauM[h * 256 + 2 * jp + 1]);
    g_wmm[i]   = pack2(WtauM[h * 256 + 128 + 2 * jp], WtauM[h * 256 + 129 + 2 * jp]);
    g_wad[i]   = pack2(WtauAdp[h * 256 + 2 * jp],       WtauAdp[h * 256 + 2 * jp + 1]);
    g_wab[i]   = pack2(WtauAdp[h * 256 + 128 + 2 * jp], WtauAdp[h * 256 + 129 + 2 * jp]);
}

__global__ void __launch_bounds__(TPB, 1)
rnn_kernel(const float* __restrict__ x,   const float* __restrict__ y,
           const float* __restrict__ h0m, const float* __restrict__ h0s,
           const float* __restrict__ h0b,
           const float* __restrict__ W1x, const float* __restrict__ b1x,
           const float* __restrict__ btauM, const float* __restrict__ btauAdp,
           const float* __restrict__ Wlin,  const float* __restrict__ blin) {
    extern __shared__ ull sh[];
    ull* sw1  = sh;                 // 64KB
    ull* swmd = sh + JP * H;        // 64KB
    ull* swad = sh + 2 * JP * H;    // 64KB
    float* aspk = (float*)(sh + 3 * JP * H);   // [MB][H]
    float* amem = aspk + MB * H;
    float* abb  = amem + MB * H;
    float* aden = abb + MB * H;

    const int tid = threadIdx.x;
    const int h   = tid & 127;          // row owned by this thread
    const int bg  = tid >> 7;           // 0..3
    const int m0  = bg * MT;            // first of 4 batch elems
    const int gmb = blockIdx.x * MB;    // global batch base

    // stage smem weights
    for (int i = tid; i < JP * H; i += TPB) {
        sw1[i]  = g_w1spk[i];
        swmd[i] = g_wmd[i];
        swad[i] = g_wad[i];
    }
    // init states
    for (int i = tid; i < MB * H; i += TPB) {
        int m = i >> 7, hh = i & 127;
        aspk[i] = h0s[(gmb + m) * H + hh];
        amem[i] = h0m[(gmb + m) * H + hh];
        abb[i]  = h0b[(gmb + m) * H + hh];
    }
    // per-row constants
    const float xw0 = W1x[h * 130 + 0];
    const float xw1 = W1x[h * 130 + 1];
    const float b1  = b1x[h];
    const float bm  = btauM[h];
    const float ba  = btauAdp[h];
    __syncthreads();

    for (int t = 0; t < SQ; t++) {
        // x_t for my 4 batch elems
        float2 xv[MT];
#pragma unroll
        for (int i = 0; i < MT; i++)
            xv[i] = *(const float2*)&x[((long)t * BATCH + gmb + m0 + i) * KD];

        // ---- phase A: dense = W1x_spk @ spk (+ x part + bias) ----
        {
            ull acc[MT];
#pragma unroll
            for (int i = 0; i < MT; i++) acc[i] = 0ull;
#pragma unroll 4
            for (int jp = 0; jp < JP; jp += 2) {
                ull w0 = sw1[jp * H + h];
                ull w1 = sw1[(jp + 1) * H + h];
#pragma unroll
                for (int i = 0; i < MT; i++) {
                    ulonglong2 av = *(const ulonglong2*)&aspk[(m0 + i) * H + 2 * jp];
                    fma2(acc[i], w0, av.x);
                    fma2(acc[i], w1, av.y);
                }
            }
#pragma unroll
            for (int i = 0; i < MT; i++) {
                float lo, hi; unpack2(acc[i], lo, hi);
                aden[(m0 + i) * H + h] = lo + hi + b1 + xw0 * xv[i].x + xw1 * xv[i].y;
            }
        }
        __syncthreads();   // dense visible

        // ---- phase B: tauM & tauA pre-activations (fused) ----
        ull accM[MT], accA[MT];
#pragma unroll
        for (int i = 0; i < MT; i++) { accM[i] = 0ull; accA[i] = 0ull; }

        // dense part: single pass over aden feeds both accumulators
#pragma unroll 4
        for (int jp = 0; jp < JP; jp += 2) {
            ull wm0 = swmd[jp * H + h];
            ull wm1 = swmd[(jp + 1) * H + h];
            ull wa0 = swad[jp * H + h];
            ull wa1 = swad[(jp + 1) * H + h];
#pragma unroll
            for (int i = 0; i < MT; i++) {
                ulonglong2 av = *(const ulonglong2*)&aden[(m0 + i) * H + 2 * jp];
                fma2(accM[i], wm0, av.x);
                fma2(accM[i], wm1, av.y);
                fma2(accA[i], wa0, av.x);
                fma2(accA[i], wa1, av.y);
            }
        }
        // streamed part: WtauM-mem and WtauAdp-bb from L2, interleaved for MLP
#pragma unroll 8
        for (int jp = 0; jp < JP; jp += 2) {
            ull wm0 = __ldg(&g_wmm[jp * H + h]);
            ull wm1 = __ldg(&g_wmm[(jp + 1) * H + h]);
            ull wa0 = __ldg(&g_wab[jp * H + h]);
            ull wa1 = __ldg(&g_wab[(jp + 1) * H + h]);
#pragma unroll
            for (int i = 0; i < MT; i++) {
                ulonglong2 avm = *(const ulonglong2*)&amem[(m0 + i) * H + 2 * jp];
                fma2(accM[i], wm0, avm.x);
                fma2(accM[i], wm1, avm.y);
                ulonglong2 avb = *(const ulonglong2*)&abb[(m0 + i) * H + 2 * jp];
                fma2(accA[i], wa0, avb.x);
                fma2(accA[i], wa1, avb.y);
            }
        }
        float tm[MT], ta[MT];
#pragma unroll
        for (int i = 0; i < MT; i++) {
            float lo, hi; unpack2(accM[i], lo, hi);
            tm[i] = sigmoid_acc(lo + hi + bm);
            unpack2(accA[i], lo, hi);
            ta[i] = sigmoid_acc(lo + hi + ba);
        }
        __syncthreads();   // all reads of mem/bb/dense/spk done

        // ---- phase C: elementwise state update (own cells only) ----
#pragma unroll
        for (int i = 0; i < MT; i++) {
            int idx = (m0 + i) * H + h;
            float sp = aspk[idx];
            float me = amem[idx];
            float bo = abb[idx];
            float de = aden[idx];
            float bbn = ta[i] * bo + (1.0f - ta[i]) * sp;
            float Bth = 0.01f + 1.8f * bbn;
            float mn  = me * tm[i] + (1.0f - tm[i]) * de - Bth * sp;
            float sn  = (mn - Bth) > 0.0f ? 1.0f : 0.0f;
            amem[idx] = mn;
            aspk[idx] = sn;
            abb[idx]  = bbn;
        }
        __syncthreads();   // states visible for next step
    }

    // ---- readout: out[m] = mem[m] . Wlin + blin ; partial sum of (out-y)^2 ----
    if (tid < MB) {
        float o = blin[0];
        for (int hh = 0; hh < H; hh++) o += amem[tid * H + hh] * Wlin[hh];
        float d = o - y[gmb + tid];
        aden[tid] = d * d;   // reuse buffer
    }
    __syncthreads();
    if (tid == 0) {
        float s = 0.0f;
        for (int i = 0; i < MB; i++) s += aden[i];
        g_partial[blockIdx.x] = s;
    }
}

__global__ void reduce_kernel(float* out) {
    __shared__ float sb[NCTA];
    sb[threadIdx.x] = g_partial[threadIdx.x];
    __syncthreads();
    if (threadIdx.x == 0) {
        float s = 0.0f;
        for (int i = 0; i < NCTA; i++) s += sb[i];
        out[0] = s / (float)BATCH;
    }
}

extern "C" void kernel_launch(void* const* d_in, const int* in_sizes, int n_in,
                              void* d_out, int out_size) {
    const float* x       = (const float*)d_in[0];
    const float* y       = (const float*)d_in[1];
    const float* h0_mem  = (const float*)d_in[2];
    const float* h0_spk  = (const float*)d_in[3];
    const float* h0_b    = (const float*)d_in[4];
    const float* W1x     = (const float*)d_in[5];
    const float* b1x     = (const float*)d_in[6];
    const float* WtauM   = (const float*)d_in[7];
    const float* btauM   = (const float*)d_in[8];
    const float* WtauAdp = (const float*)d_in[9];
    const float* btauAdp = (const float*)d_in[10];
    const float* Wlin    = (const float*)d_in[11];
    const float* blin    = (const float*)d_in[12];

    const int smem_bytes = 3 * JP * H * (int)sizeof(ull) + 4 * MB * H * (int)sizeof(float);
    static int attr_set = 0;
    if (!attr_set) {
        cudaFuncSetAttribute(rnn_kernel, cudaFuncAttributeMaxDynamicSharedMemorySize, smem_bytes);
        attr_set = 1;
    }

    pack_kernel<<<(JP * H + 255) / 256, 256>>>(W1x, WtauM, WtauAdp);
    rnn_kernel<<<NCTA, TPB, smem_bytes>>>(x, y, h0_mem, h0_spk, h0_b,
                                          W1x, b1x, btauM, btauAdp, Wlin, blin);
    reduce_kernel<<<1, NCTA>>>((float*)d_out);
}